// round 4
// baseline (speedup 1.0000x reference)
#include <cuda_runtime.h>
#include <cstdint>

// DepthDCOp: out[n,c,h,w] = sum_{kh,kw} x_pad[n,c,h+kh-1,w+kw-1] * ker[n,0,kh*3+kw,h,w]
// N=8, C=256, H=64, W=64, K=3, dilation=1.

#define N_ 8
#define C_ 256
#define H_ 64
#define W_ 64
#define HW_ (H_ * W_)
#define CPT 2   // channels per thread

__global__ __launch_bounds__(256, 4)
void ddf_kernel(const float* __restrict__ x,
                const float* __restrict__ ker,
                float* __restrict__ out)
{
    // grid.x = N*H (one (n,h) row per block), grid.y = C/(16*CPT) = 8
    const int nh = blockIdx.x;
    const int n  = nh >> 6;          // / H_
    const int h  = nh & 63;          // % H_
    const int tx = threadIdx.x;      // 0..15 -> w quad
    const int ty = threadIdx.y;      // 0..15 -> channel pair
    const int tid = ty * 16 + tx;

    // Stage the 9 per-pixel kernel rows for this (n,h): 2.25 KB, read from
    // DRAM once per block, reused by 32 channels.
    __shared__ float sk[9][W_];
    {
        const float4* kp = reinterpret_cast<const float4*>(
            ker + (size_t)n * 9 * HW_ + (size_t)h * W_);
        if (tid < 144) {
            const int t = tid >> 4;
            const int q = tid & 15;
            reinterpret_cast<float4*>(&sk[t][0])[q] = kp[(size_t)t * (HW_ / 4) + q];
        }
    }
    __syncthreads();

    const int w0 = tx << 2;
    const int c0 = (blockIdx.y << 5) + (ty << 1);   // 2 channels per thread
    const bool up_ok   = (h > 0);
    const bool down_ok = (h < H_ - 1);

    const float* xb = x + (((size_t)n * C_ + c0) * H_ + h) * W_ + w0;
    const float4 z4 = make_float4(0.f, 0.f, 0.f, 0.f);

    // ---- Batch all 6 body loads up front (MLP=6) ----
    float4 b[CPT][3];
    b[0][1] =           *reinterpret_cast<const float4*>(xb);
    b[1][1] =           *reinterpret_cast<const float4*>(xb + HW_);
    b[0][0] = up_ok   ? *reinterpret_cast<const float4*>(xb - W_)        : z4;
    b[1][0] = up_ok   ? *reinterpret_cast<const float4*>(xb + HW_ - W_)  : z4;
    b[0][2] = down_ok ? *reinterpret_cast<const float4*>(xb + W_)        : z4;
    b[1][2] = down_ok ? *reinterpret_cast<const float4*>(xb + HW_ + W_)  : z4;

    // ---- Halos via intra-segment shuffle (width 16 == one w-row of lanes) ----
    float lh[CPT][3], rh[CPT][3];
    #pragma unroll
    for (int ci = 0; ci < CPT; ci++) {
        #pragma unroll
        for (int r = 0; r < 3; r++) {
            lh[ci][r] = __shfl_up_sync(0xffffffffu,  b[ci][r].w, 1, 16);
            rh[ci][r] = __shfl_down_sync(0xffffffffu, b[ci][r].x, 1, 16);
            if (tx == 0)  lh[ci][r] = 0.f;
            if (tx == 15) rh[ci][r] = 0.f;
        }
    }

    // ---- 9 taps: one LDS.128 of kernel weights per tap, shared by both channels ----
    float acc[CPT][4];
    #pragma unroll
    for (int ci = 0; ci < CPT; ci++)
        #pragma unroll
        for (int j = 0; j < 4; j++) acc[ci][j] = 0.f;

    #pragma unroll
    for (int kh = 0; kh < 3; kh++) {
        #pragma unroll
        for (int kw = 0; kw < 3; kw++) {
            const float4 kvt =
                *reinterpret_cast<const float4*>(&sk[kh * 3 + kw][w0]);
            #pragma unroll
            for (int ci = 0; ci < CPT; ci++) {
                const float win[6] = { lh[ci][kh], b[ci][kh].x, b[ci][kh].y,
                                       b[ci][kh].z, b[ci][kh].w, rh[ci][kh] };
                acc[ci][0] = fmaf(kvt.x, win[kw + 0], acc[ci][0]);
                acc[ci][1] = fmaf(kvt.y, win[kw + 1], acc[ci][1]);
                acc[ci][2] = fmaf(kvt.z, win[kw + 2], acc[ci][2]);
                acc[ci][3] = fmaf(kvt.w, win[kw + 3], acc[ci][3]);
            }
        }
    }

    // ---- Stores ----
    float* ob = out + (((size_t)n * C_ + c0) * H_ + h) * W_ + w0;
    #pragma unroll
    for (int ci = 0; ci < CPT; ci++) {
        float4 o;
        o.x = acc[ci][0]; o.y = acc[ci][1]; o.z = acc[ci][2]; o.w = acc[ci][3];
        *reinterpret_cast<float4*>(ob + (size_t)ci * HW_) = o;
    }
}

extern "C" void kernel_launch(void* const* d_in, const int* in_sizes, int n_in,
                              void* d_out, int out_size)
{
    const float* x   = (const float*)d_in[0];   // [8,256,64,64]
    const float* ker = (const float*)d_in[1];   // [8,1,9,64,64]
    float* out = (float*)d_out;                 // [8,256,64,64]

    dim3 block(16, 16);
    dim3 grid(N_ * H_, C_ / (16 * CPT));
    ddf_kernel<<<grid, block>>>(x, ker, out);
}